// round 14
// baseline (speedup 1.0000x reference)
#include <cuda_runtime.h>
#include <stdint.h>

// out[b,h,w,:] = graph[b, slic[b,h,w]-1, :]
//   graph: [B=4, S=256, C=128] fp32  -> 128 KiB/batch, L1D-resident (no smem)
//   slic:  [B=4, 512, 512] int32     -> streamed (evict-first), prefetched 1 step
//   out:   [B, 512, 512, 128] fp32   -> 512 MiB evict-first streaming stores
//
// Block-dense write frontier: at step s, warp w writes pixels
// base + s*32 + w*4, so the whole block emits ONE contiguous 16 KiB burst
// per step and sweeps its 128 KiB range sequentially (8x fewer concurrent
// DRAM write streams chip-wide -> better HBM row locality).

static constexpr int B  = 4;
static constexpr int S  = 256;
static constexpr int C  = 128;
static constexpr int HW = 512 * 512;                  // 2^18
static constexpr int NPIX = B * HW;                   // 1,048,576

static constexpr int THREADS       = 256;             // 8 warps
static constexpr int PIX_PER_BLOCK = 256;             // 8 steps x 32 px
static constexpr int BLOCKS        = NPIX / PIX_PER_BLOCK;    // 4096

__global__ __launch_bounds__(THREADS)
void convert2image_dense_kernel(const float* __restrict__ graph,
                                const int*   __restrict__ slic,
                                float*       __restrict__ out) {
    const int warp = threadIdx.x >> 5;
    const int lane = threadIdx.x & 31;

    const int pix0 = blockIdx.x * PIX_PER_BLOCK;      // block's 256 contiguous px
    const int b    = pix0 >> 18;                      // 256 | 2^18: no straddle

    const float4* tab = reinterpret_cast<const float4*>(graph) + (size_t)b * (S * C / 4); // [S][32]
    // This warp's id pointer: one int4 (4 px) per step, stride 8 int4 / step.
    const int4* sid4 = reinterpret_cast<const int4*>(slic) + (pix0 >> 2) + warp;
    // This warp's first-pixel destination: pixel pix0 + warp*4.
    float4* dst = reinterpret_cast<float4*>(out) + ((size_t)pix0 + warp * 4) * 32 + lane;

    // Prefetch step 0's ids.
    int4 iv = __ldcs(&sid4[0]);

    #pragma unroll
    for (int step = 0; step < 8; step++) {            // 4 pixels per warp-step
        int4 nv;
        if (step < 7) nv = __ldcs(&sid4[(step + 1) * 8]);

        // 4 independent L1-hit gathers (table resident in 228 KiB L1D).
        const float4 v0 = __ldg(&tab[(iv.x - 1) * 32 + lane]);
        const float4 v1 = __ldg(&tab[(iv.y - 1) * 32 + lane]);
        const float4 v2 = __ldg(&tab[(iv.z - 1) * 32 + lane]);
        const float4 v3 = __ldg(&tab[(iv.w - 1) * 32 + lane]);

        // Warp writes 4 consecutive pixels (2 KiB); the 8 warps together
        // cover one contiguous 16 KiB block-step burst.
        float4* d = dst + (size_t)step * 32 * 32;     // advance 32 px per step
        __stcs(&d[ 0], v0);
        __stcs(&d[32], v1);
        __stcs(&d[64], v2);
        __stcs(&d[96], v3);

        iv = nv;
    }
}

extern "C" void kernel_launch(void* const* d_in, const int* in_sizes, int n_in,
                              void* d_out, int out_size) {
    const float* graph = (const float*)d_in[0];
    const int*   slic  = (const int*)d_in[1];
    float*       out   = (float*)d_out;

    convert2image_dense_kernel<<<BLOCKS, THREADS>>>(graph, slic, out);
}